// round 14
// baseline (speedup 1.0000x reference)
#include <cuda_runtime.h>
#include <cuda_fp16.h>
#include <cstdint>
#include <math_constants.h>

// ===========================================================================
// spk_vq_vae_resnet — R13 base + tiled tier2 (the 143us -> ~15us fix).
//   * argmin: fp16 HMMA (m16n8k16, f32 accum), 128-row CTAs, 16 code-tiles
//     of 128, cp.async double-buffered B, Z converted fp32->fp16 in-kernel,
//     2 CTAs/SM. Top-3 band 1e-3 + two-tier exact fp32 rescue.
//   * tier2: tiled — 16 rows/block share smem-staged W tiles (validated
//     bit-identical in the R12 run), dynamic smem.
//   * EMA sums: CSR bucket build + per-code int64 fixed-point gather
//     (order-invariant => deterministic), fused with EMA finalize.
// Outputs (concat f32): st_out [N*D] | commit_loss [1] | w_new [K*D] | c_new [K]
// ===========================================================================

#define VQ_ALPHA 0.99f
#define VQ_OMA   0.01f

constexpr int D    = 128;
constexpr int NMAX = 65536;
constexpr int KMAX = 2048;
constexpr int NTILE = 16;          // code tiles of 128
constexpr float BAND = 1e-3f;

// ---- device scratch --------------------------------------------------------
__device__ __align__(16) __half g_Wh[KMAX * D];
__device__ float  g_w2[KMAX];
__device__ int    g_idx[NMAX];
__device__ int    g_f1row[NMAX], g_f1a[NMAX], g_f1b[NMAX];
__device__ int    g_f2row[NMAX];
__device__ int    g_n1, g_n2;
__device__ int    g_counts[KMAX];
__device__ int    g_off[KMAX];
__device__ int    g_cursor[KMAX];
__device__ int    g_bucket[NMAX];
__device__ double g_loss;

// ---- helpers ---------------------------------------------------------------
__device__ __forceinline__ uint32_t smem_u32(const void* p) {
    uint32_t a;
    asm("{ .reg .u64 t; cvta.to.shared.u64 t, %1; cvt.u32.u64 %0, t; }"
        : "=r"(a) : "l"(p));
    return a;
}
__device__ __forceinline__ void cp_async16(uint32_t smem_dst, const void* gsrc) {
    asm volatile("cp.async.cg.shared.global [%0], [%1], 16;" :: "r"(smem_dst), "l"(gsrc));
}
__device__ __forceinline__ void cp_commit() { asm volatile("cp.async.commit_group;"); }
template <int NN>
__device__ __forceinline__ void cp_wait() { asm volatile("cp.async.wait_group %0;" :: "n"(NN)); }

__device__ __forceinline__ void ldsm4(uint32_t& r0, uint32_t& r1, uint32_t& r2,
                                      uint32_t& r3, uint32_t addr) {
    asm volatile("ldmatrix.sync.aligned.m8n8.x4.shared.b16 {%0,%1,%2,%3}, [%4];"
                 : "=r"(r0), "=r"(r1), "=r"(r2), "=r"(r3) : "r"(addr));
}
__device__ __forceinline__ void mma16816(float* c, uint32_t a0, uint32_t a1,
                                         uint32_t a2, uint32_t a3,
                                         uint32_t b0, uint32_t b1) {
    asm volatile(
        "mma.sync.aligned.m16n8k16.row.col.f32.f16.f16.f32 "
        "{%0,%1,%2,%3}, {%4,%5,%6,%7}, {%8,%9}, {%0,%1,%2,%3};"
        : "+f"(c[0]), "+f"(c[1]), "+f"(c[2]), "+f"(c[3])
        : "r"(a0), "r"(a1), "r"(a2), "r"(a3), "r"(b0), "r"(b1));
}

// top-3 insert, lowest-index preference on exact ties
__device__ __forceinline__ void ins3(float s, int c,
                                     float& b1, int& i1, float& b2, int& i2,
                                     float& b3, int& i3) {
    if (s < b1 || (s == b1 && c < i1)) {
        b3 = b2; i3 = i2; b2 = b1; i2 = i1; b1 = s; i1 = c;
    } else if (s < b2 || (s == b2 && c < i2)) {
        b3 = b2; i3 = i2; b2 = s; i2 = c;
    } else if (s < b3 || (s == b3 && c < i3)) {
        b3 = s; i3 = c;
    }
}

// ---------------------------------------------------------------------------

// W fp32->fp16 + w2; block 0 also zeroes the small counters (fused zero).
__global__ void prep_kernel(const float* __restrict__ W, int K) {
    if (blockIdx.x == 0) {
        for (int j = threadIdx.x; j < K; j += blockDim.x) {
            g_counts[j] = 0; g_cursor[j] = 0;
        }
        if (threadIdx.x == 0) { g_loss = 0.0; g_n1 = 0; g_n2 = 0; }
    }
    int g    = (blockIdx.x * blockDim.x + threadIdx.x) >> 5;
    int lane = threadIdx.x & 31;
    if (g >= K) return;
    const float* src = W + (size_t)g * D;
    float4 v = ((const float4*)src)[lane];
    __half2 h01 = __floats2half2_rn(v.x, v.y);
    __half2 h23 = __floats2half2_rn(v.z, v.w);
    uint2 u = { *(uint32_t*)&h01, *(uint32_t*)&h23 };
    *(uint2*)(g_Wh + (size_t)g * D + lane * 4) = u;
    float s = 0.f;
    s = fmaf(v.x, v.x, s); s = fmaf(v.y, v.y, s);
    s = fmaf(v.z, v.z, s); s = fmaf(v.w, v.w, s);
    #pragma unroll
    for (int off = 16; off; off >>= 1) s += __shfl_xor_sync(0xffffffffu, s, off);
    if (lane == 0) g_w2[g] = s;
}

// ---- fp16 HMMA argmin, f32 accum, 128-code tiles, 2 CTAs/SM ----------------
// smem layout: Zs 32KB | Bs 2x32KB | w2s 8KB = 106496 B total
constexpr int SM_Z  = 0;
constexpr int SM_B0 = 32768;
constexpr int SM_W2 = 98304;
constexpr int SMEM_ARG = SM_W2 + KMAX * 4;   // 106496 bytes

// XOR-swizzled address (rows of 16 x 16B chunks, conflict-free ldsm)
__device__ __forceinline__ uint32_t sw_addr(uint32_t base, int r, int c) {
    return base + r * 256 + ((c ^ (r & 7)) << 4);
}

__global__ __launch_bounds__(256, 2)
void argmin_hmma_kernel(const float* __restrict__ Z) {
    extern __shared__ char sm[];
    const uint32_t sb = smem_u32(sm);
    float* w2s = (float*)(sm + SM_W2);
    const int tid  = threadIdx.x;
    const int lane = tid & 31;
    const int wid  = tid >> 5;
    const int warpRow = wid * 16;
    const int row0 = blockIdx.x * 128;

    // async: B tile 0 (group 0), B tile 1 (group 1)
    for (int i = tid; i < 2048; i += 256) {
        int r = i >> 4, c = i & 15;
        cp_async16(sw_addr(sb + SM_B0, r, c), g_Wh + (size_t)r * D + c * 8);
    }
    cp_commit();
    for (int i = tid; i < 2048; i += 256) {
        int r = i >> 4, c = i & 15;
        cp_async16(sw_addr(sb + SM_B0 + 32768, r, c),
                   g_Wh + (size_t)(128 + r) * D + c * 8);
    }
    cp_commit();

    // while B copies fly: stage w2 and convert this CTA's Z rows fp32->fp16
    for (int i = tid; i < KMAX; i += 256) w2s[i] = g_w2[i];
    {
        const float* Zb = Z + (size_t)row0 * D;
        #pragma unroll 4
        for (int i = tid; i < 4096; i += 256) {      // 128 rows x 32 float4
            int r = i >> 5, j = i & 31;
            float4 v = *(const float4*)(Zb + (size_t)r * D + j * 4);
            __half2 h01 = __floats2half2_rn(v.x, v.y);
            __half2 h23 = __floats2half2_rn(v.z, v.w);
            uint32_t addr = sw_addr(sb + SM_Z, r, j >> 1) + (j & 1) * 8;
            asm volatile("st.shared.v2.b32 [%0], {%1,%2};"
                         :: "r"(addr), "r"(*(uint32_t*)&h01), "r"(*(uint32_t*)&h23));
        }
    }

    float B1[2] = {CUDART_INF_F, CUDART_INF_F};
    float B2[2] = {CUDART_INF_F, CUDART_INF_F};
    float B3[2] = {CUDART_INF_F, CUDART_INF_F};
    int   I1[2] = {0x7fffffff, 0x7fffffff};
    int   I2[2] = {0x7fffffff, 0x7fffffff};
    int   I3[2] = {0x7fffffff, 0x7fffffff};

    const int m  = lane >> 3;
    const int r8 = lane & 7;

    for (int t = 0; t < NTILE; t++) {
        if (t < NTILE - 1) cp_wait<1>(); else cp_wait<0>();
        __syncthreads();                       // B[t] + Z(t==0) visible
        const uint32_t bbase = sb + SM_B0 + (t & 1) * 32768;

        float acc[16][4];
        #pragma unroll
        for (int f = 0; f < 16; f++)
            #pragma unroll
            for (int q = 0; q < 4; q++) acc[f][q] = 0.f;

        #pragma unroll
        for (int ks = 0; ks < 8; ks++) {
            uint32_t a0, a1, a2, a3;
            {
                int row = warpRow + ((m & 1) << 3) + r8;
                int ch  = 2 * ks + (m >> 1);
                ldsm4(a0, a1, a2, a3, sw_addr(sb + SM_Z, row, ch));
            }
            #pragma unroll
            for (int nf = 0; nf < 16; nf += 2) {
                uint32_t c0, c1, c2, c3;
                {
                    int code = nf * 8 + ((m >> 1) << 3) + r8;
                    int ch   = 2 * ks + (m & 1);
                    ldsm4(c0, c1, c2, c3, sw_addr(bbase, code, ch));
                }
                mma16816(acc[nf],     a0, a1, a2, a3, c0, c1);
                mma16816(acc[nf + 1], a0, a1, a2, a3, c2, c3);
            }
        }

        __syncthreads();                       // all warps done reading B[t]

        if (t < NTILE - 2) {
            const __half* src = g_Wh + (size_t)(t + 2) * 128 * D;
            uint32_t dstb = sb + SM_B0 + (t & 1) * 32768;
            for (int i = tid; i < 2048; i += 256) {
                int r = i >> 4, c = i & 15;
                cp_async16(sw_addr(dstb, r, c), src + (size_t)r * D + c * 8);
            }
            cp_commit();
        }

        // epilogue: s = w2 - 2*zw; rows r0 = warpRow+(lane>>2), r1 = r0+8
        #pragma unroll
        for (int f = 0; f < 16; f++) {
            int cb0 = t * 128 + f * 8 + 2 * (lane & 3);
            float w2a = w2s[cb0], w2b = w2s[cb0 + 1];
            float s;
            s = fmaf(-2.f, acc[f][0], w2a);
            ins3(s, cb0,     B1[0], I1[0], B2[0], I2[0], B3[0], I3[0]);
            s = fmaf(-2.f, acc[f][1], w2b);
            ins3(s, cb0 + 1, B1[0], I1[0], B2[0], I2[0], B3[0], I3[0]);
            s = fmaf(-2.f, acc[f][2], w2a);
            ins3(s, cb0,     B1[1], I1[1], B2[1], I2[1], B3[1], I3[1]);
            s = fmaf(-2.f, acc[f][3], w2b);
            ins3(s, cb0 + 1, B1[1], I1[1], B2[1], I2[1], B3[1], I3[1]);
        }
    }

    // merge top-3 across the 4 lanes of each quad (same rows)
    #pragma unroll
    for (int off = 1; off <= 2; off <<= 1) {
        #pragma unroll
        for (int r = 0; r < 2; r++) {
            float v1 = __shfl_xor_sync(0xffffffffu, B1[r], off);
            int   j1 = __shfl_xor_sync(0xffffffffu, I1[r], off);
            float v2 = __shfl_xor_sync(0xffffffffu, B2[r], off);
            int   j2 = __shfl_xor_sync(0xffffffffu, I2[r], off);
            float v3 = __shfl_xor_sync(0xffffffffu, B3[r], off);
            int   j3 = __shfl_xor_sync(0xffffffffu, I3[r], off);
            ins3(v1, j1, B1[r], I1[r], B2[r], I2[r], B3[r], I3[r]);
            ins3(v2, j2, B1[r], I1[r], B2[r], I2[r], B3[r], I3[r]);
            ins3(v3, j3, B1[r], I1[r], B2[r], I2[r], B3[r], I3[r]);
        }
    }

    if ((lane & 3) == 0) {
        #pragma unroll
        for (int r = 0; r < 2; r++) {
            int row = row0 + warpRow + (lane >> 2) + r * 8;
            g_idx[row] = I1[r];
            if (__fsub_rn(B3[r], B1[r]) < BAND) {
                int p = atomicAdd(&g_n2, 1);
                g_f2row[p] = row;
            } else if (__fsub_rn(B2[r], B1[r]) < BAND) {
                int p = atomicAdd(&g_n1, 1);
                g_f1row[p] = row; g_f1a[p] = I1[r]; g_f1b[p] = I2[r];
            }
        }
    }
}

// ---- tier 1: exact fp32 compare of the two in-band candidates --------------
__global__ void tier1_kernel(const float* __restrict__ Z,
                             const float* __restrict__ W) {
    int n1 = g_n1;
    int wg = (blockIdx.x * blockDim.x + threadIdx.x) >> 5;
    int lane = threadIdx.x & 31;
    int nwarps = (gridDim.x * blockDim.x) >> 5;
    for (int e = wg; e < n1; e += nwarps) {
        int row = g_f1row[e], ca = g_f1a[e], cb = g_f1b[e];
        float4 zv = ((const float4*)(Z + (size_t)row * D))[lane];
        float4 av = ((const float4*)(W + (size_t)ca * D))[lane];
        float4 bv = ((const float4*)(W + (size_t)cb * D))[lane];
        float z2 = 0.f, da = 0.f, db = 0.f;
        z2 = fmaf(zv.x, zv.x, z2); z2 = fmaf(zv.y, zv.y, z2);
        z2 = fmaf(zv.z, zv.z, z2); z2 = fmaf(zv.w, zv.w, z2);
        da = fmaf(zv.x, av.x, da); da = fmaf(zv.y, av.y, da);
        da = fmaf(zv.z, av.z, da); da = fmaf(zv.w, av.w, da);
        db = fmaf(zv.x, bv.x, db); db = fmaf(zv.y, bv.y, db);
        db = fmaf(zv.z, bv.z, db); db = fmaf(zv.w, bv.w, db);
        #pragma unroll
        for (int off = 16; off; off >>= 1) {
            z2 += __shfl_xor_sync(0xffffffffu, z2, off);
            da += __shfl_xor_sync(0xffffffffu, da, off);
            db += __shfl_xor_sync(0xffffffffu, db, off);
        }
        if (lane == 0) {
            float dista = __fadd_rn(__fsub_rn(z2, __fmul_rn(2.f, da)), g_w2[ca]);
            float distb = __fadd_rn(__fsub_rn(z2, __fmul_rn(2.f, db)), g_w2[cb]);
            g_idx[row] = (distb < dista || (distb == dista && cb < ca)) ? cb : ca;
        }
    }
}

// ---- tier 2: tiled full-K exact recompute (16 rows/block share W tiles) ----
// Dynamic smem: zsT [128][17] floats + wt [64][132] floats = 68608 bytes.
constexpr int T2_ZST  = 128 * 17;
constexpr int T2_WT   = 64 * 132;
constexpr int T2_SMEM = (T2_ZST + T2_WT) * 4;   // 68608

__global__ __launch_bounds__(256)
void tier2_kernel(const float* __restrict__ Z, const float* __restrict__ W) {
    extern __shared__ float dyn[];
    float (*zsT)[17]  = (float(*)[17])dyn;               // transposed z rows
    float (*wt)[132]  = (float(*)[132])(dyn + T2_ZST);   // staged W tile
    __shared__ float z2s[16];
    __shared__ int   ridx[16];
    __shared__ float rv[16][16];
    __shared__ int   ri[16][16];
    const int tid = threadIdx.x;
    int n2 = g_n2;

    for (int base = blockIdx.x * 16; base < n2; base += gridDim.x * 16) {
        int nr = min(16, n2 - base);
        __syncthreads();               // smem reuse across grid-stride iters
        if (tid < nr) ridx[tid] = g_f2row[base + tid];
        __syncthreads();
        // stage z rows (transposed)
        for (int i = tid; i < nr * 32; i += 256) {
            int r = i >> 5, l = i & 31;
            float4 v = ((const float4*)(Z + (size_t)ridx[r] * D))[l];
            zsT[l * 4 + 0][r] = v.x; zsT[l * 4 + 1][r] = v.y;
            zsT[l * 4 + 2][r] = v.z; zsT[l * 4 + 3][r] = v.w;
        }
        __syncthreads();
        // z2 via the exact sequential chain
        if (tid < nr) {
            float z2 = 0.f;
            #pragma unroll 8
            for (int d = 0; d < 128; d++)
                z2 = __fadd_rn(z2, __fmul_rn(zsT[d][tid], zsT[d][tid]));
            z2s[tid] = z2;
        }

        const int rr = tid >> 4, cc = tid & 15;
        float bd = CUDART_INF_F; int bi = 0x7fffffff;

        for (int kt = 0; kt < 32; kt++) {      // 32 W tiles of 64 codes
            int kb = kt * 64;
            __syncthreads();
            for (int i = tid; i < 64 * 32; i += 256) {
                int c = i >> 5, l = i & 31;
                float4 wv = ((const float4*)(W + (size_t)(kb + c) * D))[l];
                *(float4*)&wt[c][l * 4] = wv;
            }
            __syncthreads();
            if (rr < nr) {
                #pragma unroll
                for (int k = 0; k < 4; k++) {
                    int cl = cc + 16 * k;
                    float acc = 0.f;
                    #pragma unroll 4
                    for (int d4 = 0; d4 < 32; d4++) {
                        float4 w = *(const float4*)&wt[cl][d4 * 4];
                        acc = fmaf(zsT[d4 * 4 + 0][rr], w.x, acc);
                        acc = fmaf(zsT[d4 * 4 + 1][rr], w.y, acc);
                        acc = fmaf(zsT[d4 * 4 + 2][rr], w.z, acc);
                        acc = fmaf(zsT[d4 * 4 + 3][rr], w.w, acc);
                    }
                    int code = kb + cl;
                    float dist = __fadd_rn(__fsub_rn(z2s[rr], __fmul_rn(2.f, acc)),
                                           g_w2[code]);
                    if (dist < bd || (dist == bd && code < bi)) { bd = dist; bi = code; }
                }
            }
        }
        rv[rr][cc] = bd; ri[rr][cc] = bi;
        __syncthreads();
        if (tid < nr) {
            float v = rv[tid][0]; int j = ri[tid][0];
            #pragma unroll
            for (int c = 1; c < 16; c++) {
                float v2 = rv[tid][c]; int j2 = ri[tid][c];
                if (v2 < v || (v2 == v && j2 < j)) { v = v2; j = j2; }
            }
            g_idx[ridx[tid]] = j;
        }
        bd = CUDART_INF_F; bi = 0x7fffffff;    // reset for next chunk
    }
}

// ---- CSR bucket build: count -> prefix -> place ----------------------------
__global__ void count_kernel(int N) {
    int i = blockIdx.x * blockDim.x + threadIdx.x;
    if (i < N) atomicAdd(&g_counts[g_idx[i]], 1);
}

__global__ void prefix_kernel() {
    __shared__ int part[256];
    int t = threadIdx.x;
    int base = t * 8;
    int loc[8];
    int s = 0;
    #pragma unroll
    for (int i = 0; i < 8; i++) { loc[i] = s; s += g_counts[base + i]; }
    part[t] = s;
    __syncthreads();
    for (int off = 1; off < 256; off <<= 1) {
        int x = (t >= off) ? part[t - off] : 0;
        __syncthreads();
        part[t] += x;
        __syncthreads();
    }
    int excl = part[t] - s;
    #pragma unroll
    for (int i = 0; i < 8; i++) g_off[base + i] = excl + loc[i];
}

__global__ void place_kernel(int N) {
    int i = blockIdx.x * blockDim.x + threadIdx.x;
    if (i < N) {
        int j = g_idx[i];
        int slot = atomicAdd(&g_cursor[j], 1);
        g_bucket[g_off[j] + slot] = i;
    }
}

// ---- per-code int64 fixed-point gather-sum + EMA finalize ------------------
__global__ void codesum_kernel(const float* __restrict__ Z,
                               const float* __restrict__ Wold,
                               const float* __restrict__ Cold,
                               float* __restrict__ out_w,
                               float* __restrict__ out_c) {
    int k = blockIdx.x;
    int d = threadIdx.x;
    int cnt = g_counts[k];
    int off = g_off[k];
    float c_old = Cold[k];
    float c_new = (cnt > 0)
        ? __fadd_rn(__fmul_rn(VQ_ALPHA, c_old), __fmul_rn(VQ_OMA, (float)cnt))
        : c_old;
    if (d == 0) out_c[k] = c_new;

    float w = Wold[(size_t)k * D + d];
    float wn = w;
    if (cnt > 0) {
        long long afx = 0;
        int i = 0;
        for (; i + 1 < cnt; i += 2) {
            int r0 = g_bucket[off + i];
            int r1 = g_bucket[off + i + 1];
            afx += (long long)llrintf(Z[(size_t)r0 * D + d] * 1048576.0f)
                 + (long long)llrintf(Z[(size_t)r1 * D + d] * 1048576.0f);
        }
        if (i < cnt) {
            int r0 = g_bucket[off + i];
            afx += (long long)llrintf(Z[(size_t)r0 * D + d] * 1048576.0f);
        }
        float s  = (float)((double)afx * (1.0 / 1048576.0));
        float cm = fmaxf(c_new, 1e-12f);
        wn = __fadd_rn(__fmul_rn(VQ_ALPHA, w),
                       __fdiv_rn(__fmul_rn(VQ_OMA, s), cm));
    }
    out_w[(size_t)k * D + d] = wn;
}

// st_out = z + (w_new[i]-z); commit loss partials -> one double atomic/block.
__global__ void gather_loss_kernel(const float* __restrict__ Z,
                                   const float* __restrict__ Wn,
                                   float* __restrict__ out_st, int N) {
    int d   = threadIdx.x & 127;
    int sub = threadIdx.x >> 7;
    float accl = 0.f;
    for (int n = blockIdx.x * 2 + sub; n < N; n += gridDim.x * 2) {
        int j = g_idx[n];
        float w = Wn[(size_t)j * D + d];
        float z = Z[(size_t)n * D + d];
        out_st[(size_t)n * D + d] = __fadd_rn(z, __fsub_rn(w, z));
        float df = __fsub_rn(z, w);
        accl = fmaf(df, df, accl);
    }
    __shared__ float red[8];
    float s = accl;
    #pragma unroll
    for (int off = 16; off; off >>= 1) s += __shfl_xor_sync(0xffffffffu, s, off);
    if ((threadIdx.x & 31) == 0) red[threadIdx.x >> 5] = s;
    __syncthreads();
    if (threadIdx.x == 0) {
        float tot = ((red[0] + red[1]) + (red[2] + red[3]))
                  + ((red[4] + red[5]) + (red[6] + red[7]));
        atomicAdd(&g_loss, (double)tot);
    }
}

__global__ void loss_write_kernel(float* out_loss, int N) {
    *out_loss = (float)(g_loss / (double)N);
}

// ---------------------------------------------------------------------------

extern "C" void kernel_launch(void* const* d_in, const int* in_sizes, int n_in,
                              void* d_out, int out_size) {
    const float* Z = (const float*)d_in[0];
    const float* W = (const float*)d_in[1];
    const float* C = (const float*)d_in[2];
    const int N = in_sizes[0] / D;       // 65536
    const int K = in_sizes[2];           // 2048

    float* out      = (float*)d_out;
    float* out_st   = out;                           // [N*D]
    float* out_loss = out + (size_t)N * D;           // [1]
    float* out_w    = out_loss + 1;                  // [K*D]
    float* out_c    = out_w + (size_t)K * D;         // [K]

    static bool attr_done = false;
    if (!attr_done) {
        cudaFuncSetAttribute(argmin_hmma_kernel,
                             cudaFuncAttributeMaxDynamicSharedMemorySize, SMEM_ARG);
        cudaFuncSetAttribute(tier2_kernel,
                             cudaFuncAttributeMaxDynamicSharedMemorySize, T2_SMEM);
        attr_done = true;
    }

    prep_kernel<<<(K * 32 + 255) / 256, 256>>>(W, K);
    argmin_hmma_kernel<<<N / 128, 256, SMEM_ARG>>>(Z);
    tier1_kernel<<<256, 256>>>(Z, W);
    tier2_kernel<<<128, 256, T2_SMEM>>>(Z, W);
    count_kernel<<<N / 256, 256>>>(N);
    prefix_kernel<<<1, 256>>>();
    place_kernel<<<N / 256, 256>>>(N);
    codesum_kernel<<<K, D>>>(Z, W, C, out_w, out_c);
    gather_loss_kernel<<<4096, 256>>>(Z, out_w, out_st, N);
    loss_write_kernel<<<1, 1>>>(out_loss, N);
}

// round 15
// speedup vs baseline: 1.2895x; 1.2895x over previous
#include <cuda_runtime.h>
#include <cuda_fp16.h>
#include <cstdint>
#include <math_constants.h>

// ===========================================================================
// spk_vq_vae_resnet — R13 base + warp-per-chunk tier2 (tier1's proven shape).
//   * argmin: fp16 HMMA (m16n8k16, f32 accum), 128-row CTAs, 16 code-tiles
//     of 128, cp.async double-buffered B, Z converted fp32->fp16 in-kernel,
//     2 CTAs/SM. Top-3 band 1e-3 + two-tier exact fp32 rescue.
//   * tier2: one block per flagged row; 8 warps x 256 codes; lanes split D
//     (coalesced float4), shfl dot-reduce, block-reduce. ~10us for ~150 rows.
//   * EMA sums: CSR bucket build + per-code int64 fixed-point gather
//     (order-invariant => deterministic), fused with EMA finalize.
// Outputs (concat f32): st_out [N*D] | commit_loss [1] | w_new [K*D] | c_new [K]
// ===========================================================================

#define VQ_ALPHA 0.99f
#define VQ_OMA   0.01f

constexpr int D    = 128;
constexpr int NMAX = 65536;
constexpr int KMAX = 2048;
constexpr int NTILE = 16;          // code tiles of 128
constexpr float BAND = 1e-3f;

// ---- device scratch --------------------------------------------------------
__device__ __align__(16) __half g_Wh[KMAX * D];
__device__ float  g_w2[KMAX];
__device__ int    g_idx[NMAX];
__device__ int    g_f1row[NMAX], g_f1a[NMAX], g_f1b[NMAX];
__device__ int    g_f2row[NMAX];
__device__ int    g_n1, g_n2;
__device__ int    g_counts[KMAX];
__device__ int    g_off[KMAX];
__device__ int    g_cursor[KMAX];
__device__ int    g_bucket[NMAX];
__device__ double g_loss;

// ---- helpers ---------------------------------------------------------------
__device__ __forceinline__ uint32_t smem_u32(const void* p) {
    uint32_t a;
    asm("{ .reg .u64 t; cvta.to.shared.u64 t, %1; cvt.u32.u64 %0, t; }"
        : "=r"(a) : "l"(p));
    return a;
}
__device__ __forceinline__ void cp_async16(uint32_t smem_dst, const void* gsrc) {
    asm volatile("cp.async.cg.shared.global [%0], [%1], 16;" :: "r"(smem_dst), "l"(gsrc));
}
__device__ __forceinline__ void cp_commit() { asm volatile("cp.async.commit_group;"); }
template <int NN>
__device__ __forceinline__ void cp_wait() { asm volatile("cp.async.wait_group %0;" :: "n"(NN)); }

__device__ __forceinline__ void ldsm4(uint32_t& r0, uint32_t& r1, uint32_t& r2,
                                      uint32_t& r3, uint32_t addr) {
    asm volatile("ldmatrix.sync.aligned.m8n8.x4.shared.b16 {%0,%1,%2,%3}, [%4];"
                 : "=r"(r0), "=r"(r1), "=r"(r2), "=r"(r3) : "r"(addr));
}
__device__ __forceinline__ void mma16816(float* c, uint32_t a0, uint32_t a1,
                                         uint32_t a2, uint32_t a3,
                                         uint32_t b0, uint32_t b1) {
    asm volatile(
        "mma.sync.aligned.m16n8k16.row.col.f32.f16.f16.f32 "
        "{%0,%1,%2,%3}, {%4,%5,%6,%7}, {%8,%9}, {%0,%1,%2,%3};"
        : "+f"(c[0]), "+f"(c[1]), "+f"(c[2]), "+f"(c[3])
        : "r"(a0), "r"(a1), "r"(a2), "r"(a3), "r"(b0), "r"(b1));
}

// top-3 insert, lowest-index preference on exact ties
__device__ __forceinline__ void ins3(float s, int c,
                                     float& b1, int& i1, float& b2, int& i2,
                                     float& b3, int& i3) {
    if (s < b1 || (s == b1 && c < i1)) {
        b3 = b2; i3 = i2; b2 = b1; i2 = i1; b1 = s; i1 = c;
    } else if (s < b2 || (s == b2 && c < i2)) {
        b3 = b2; i3 = i2; b2 = s; i2 = c;
    } else if (s < b3 || (s == b3 && c < i3)) {
        b3 = s; i3 = c;
    }
}

// ---------------------------------------------------------------------------

// W fp32->fp16 + w2; block 0 also zeroes the small counters (fused zero).
__global__ void prep_kernel(const float* __restrict__ W, int K) {
    if (blockIdx.x == 0) {
        for (int j = threadIdx.x; j < K; j += blockDim.x) {
            g_counts[j] = 0; g_cursor[j] = 0;
        }
        if (threadIdx.x == 0) { g_loss = 0.0; g_n1 = 0; g_n2 = 0; }
    }
    int g    = (blockIdx.x * blockDim.x + threadIdx.x) >> 5;
    int lane = threadIdx.x & 31;
    if (g >= K) return;
    const float* src = W + (size_t)g * D;
    float4 v = ((const float4*)src)[lane];
    __half2 h01 = __floats2half2_rn(v.x, v.y);
    __half2 h23 = __floats2half2_rn(v.z, v.w);
    uint2 u = { *(uint32_t*)&h01, *(uint32_t*)&h23 };
    *(uint2*)(g_Wh + (size_t)g * D + lane * 4) = u;
    float s = 0.f;
    s = fmaf(v.x, v.x, s); s = fmaf(v.y, v.y, s);
    s = fmaf(v.z, v.z, s); s = fmaf(v.w, v.w, s);
    #pragma unroll
    for (int off = 16; off; off >>= 1) s += __shfl_xor_sync(0xffffffffu, s, off);
    if (lane == 0) g_w2[g] = s;
}

// ---- fp16 HMMA argmin, f32 accum, 128-code tiles, 2 CTAs/SM ----------------
// smem layout: Zs 32KB | Bs 2x32KB | w2s 8KB = 106496 B total
constexpr int SM_Z  = 0;
constexpr int SM_B0 = 32768;
constexpr int SM_W2 = 98304;
constexpr int SMEM_ARG = SM_W2 + KMAX * 4;   // 106496 bytes

// XOR-swizzled address (rows of 16 x 16B chunks, conflict-free ldsm)
__device__ __forceinline__ uint32_t sw_addr(uint32_t base, int r, int c) {
    return base + r * 256 + ((c ^ (r & 7)) << 4);
}

__global__ __launch_bounds__(256, 2)
void argmin_hmma_kernel(const float* __restrict__ Z) {
    extern __shared__ char sm[];
    const uint32_t sb = smem_u32(sm);
    float* w2s = (float*)(sm + SM_W2);
    const int tid  = threadIdx.x;
    const int lane = tid & 31;
    const int wid  = tid >> 5;
    const int warpRow = wid * 16;
    const int row0 = blockIdx.x * 128;

    // async: B tile 0 (group 0), B tile 1 (group 1)
    for (int i = tid; i < 2048; i += 256) {
        int r = i >> 4, c = i & 15;
        cp_async16(sw_addr(sb + SM_B0, r, c), g_Wh + (size_t)r * D + c * 8);
    }
    cp_commit();
    for (int i = tid; i < 2048; i += 256) {
        int r = i >> 4, c = i & 15;
        cp_async16(sw_addr(sb + SM_B0 + 32768, r, c),
                   g_Wh + (size_t)(128 + r) * D + c * 8);
    }
    cp_commit();

    // while B copies fly: stage w2 and convert this CTA's Z rows fp32->fp16
    for (int i = tid; i < KMAX; i += 256) w2s[i] = g_w2[i];
    {
        const float* Zb = Z + (size_t)row0 * D;
        #pragma unroll 4
        for (int i = tid; i < 4096; i += 256) {      // 128 rows x 32 float4
            int r = i >> 5, j = i & 31;
            float4 v = *(const float4*)(Zb + (size_t)r * D + j * 4);
            __half2 h01 = __floats2half2_rn(v.x, v.y);
            __half2 h23 = __floats2half2_rn(v.z, v.w);
            uint32_t addr = sw_addr(sb + SM_Z, r, j >> 1) + (j & 1) * 8;
            asm volatile("st.shared.v2.b32 [%0], {%1,%2};"
                         :: "r"(addr), "r"(*(uint32_t*)&h01), "r"(*(uint32_t*)&h23));
        }
    }

    float B1[2] = {CUDART_INF_F, CUDART_INF_F};
    float B2[2] = {CUDART_INF_F, CUDART_INF_F};
    float B3[2] = {CUDART_INF_F, CUDART_INF_F};
    int   I1[2] = {0x7fffffff, 0x7fffffff};
    int   I2[2] = {0x7fffffff, 0x7fffffff};
    int   I3[2] = {0x7fffffff, 0x7fffffff};

    const int m  = lane >> 3;
    const int r8 = lane & 7;

    for (int t = 0; t < NTILE; t++) {
        if (t < NTILE - 1) cp_wait<1>(); else cp_wait<0>();
        __syncthreads();                       // B[t] + Z(t==0) visible
        const uint32_t bbase = sb + SM_B0 + (t & 1) * 32768;

        float acc[16][4];
        #pragma unroll
        for (int f = 0; f < 16; f++)
            #pragma unroll
            for (int q = 0; q < 4; q++) acc[f][q] = 0.f;

        #pragma unroll
        for (int ks = 0; ks < 8; ks++) {
            uint32_t a0, a1, a2, a3;
            {
                int row = warpRow + ((m & 1) << 3) + r8;
                int ch  = 2 * ks + (m >> 1);
                ldsm4(a0, a1, a2, a3, sw_addr(sb + SM_Z, row, ch));
            }
            #pragma unroll
            for (int nf = 0; nf < 16; nf += 2) {
                uint32_t c0, c1, c2, c3;
                {
                    int code = nf * 8 + ((m >> 1) << 3) + r8;
                    int ch   = 2 * ks + (m & 1);
                    ldsm4(c0, c1, c2, c3, sw_addr(bbase, code, ch));
                }
                mma16816(acc[nf],     a0, a1, a2, a3, c0, c1);
                mma16816(acc[nf + 1], a0, a1, a2, a3, c2, c3);
            }
        }

        __syncthreads();                       // all warps done reading B[t]

        if (t < NTILE - 2) {
            const __half* src = g_Wh + (size_t)(t + 2) * 128 * D;
            uint32_t dstb = sb + SM_B0 + (t & 1) * 32768;
            for (int i = tid; i < 2048; i += 256) {
                int r = i >> 4, c = i & 15;
                cp_async16(sw_addr(dstb, r, c), src + (size_t)r * D + c * 8);
            }
            cp_commit();
        }

        // epilogue: s = w2 - 2*zw; rows r0 = warpRow+(lane>>2), r1 = r0+8
        #pragma unroll
        for (int f = 0; f < 16; f++) {
            int cb0 = t * 128 + f * 8 + 2 * (lane & 3);
            float w2a = w2s[cb0], w2b = w2s[cb0 + 1];
            float s;
            s = fmaf(-2.f, acc[f][0], w2a);
            ins3(s, cb0,     B1[0], I1[0], B2[0], I2[0], B3[0], I3[0]);
            s = fmaf(-2.f, acc[f][1], w2b);
            ins3(s, cb0 + 1, B1[0], I1[0], B2[0], I2[0], B3[0], I3[0]);
            s = fmaf(-2.f, acc[f][2], w2a);
            ins3(s, cb0,     B1[1], I1[1], B2[1], I2[1], B3[1], I3[1]);
            s = fmaf(-2.f, acc[f][3], w2b);
            ins3(s, cb0 + 1, B1[1], I1[1], B2[1], I2[1], B3[1], I3[1]);
        }
    }

    // merge top-3 across the 4 lanes of each quad (same rows)
    #pragma unroll
    for (int off = 1; off <= 2; off <<= 1) {
        #pragma unroll
        for (int r = 0; r < 2; r++) {
            float v1 = __shfl_xor_sync(0xffffffffu, B1[r], off);
            int   j1 = __shfl_xor_sync(0xffffffffu, I1[r], off);
            float v2 = __shfl_xor_sync(0xffffffffu, B2[r], off);
            int   j2 = __shfl_xor_sync(0xffffffffu, I2[r], off);
            float v3 = __shfl_xor_sync(0xffffffffu, B3[r], off);
            int   j3 = __shfl_xor_sync(0xffffffffu, I3[r], off);
            ins3(v1, j1, B1[r], I1[r], B2[r], I2[r], B3[r], I3[r]);
            ins3(v2, j2, B1[r], I1[r], B2[r], I2[r], B3[r], I3[r]);
            ins3(v3, j3, B1[r], I1[r], B2[r], I2[r], B3[r], I3[r]);
        }
    }

    if ((lane & 3) == 0) {
        #pragma unroll
        for (int r = 0; r < 2; r++) {
            int row = row0 + warpRow + (lane >> 2) + r * 8;
            g_idx[row] = I1[r];
            if (__fsub_rn(B3[r], B1[r]) < BAND) {
                int p = atomicAdd(&g_n2, 1);
                g_f2row[p] = row;
            } else if (__fsub_rn(B2[r], B1[r]) < BAND) {
                int p = atomicAdd(&g_n1, 1);
                g_f1row[p] = row; g_f1a[p] = I1[r]; g_f1b[p] = I2[r];
            }
        }
    }
}

// ---- tier 1: exact fp32 compare of the two in-band candidates --------------
__global__ void tier1_kernel(const float* __restrict__ Z,
                             const float* __restrict__ W) {
    int n1 = g_n1;
    int wg = (blockIdx.x * blockDim.x + threadIdx.x) >> 5;
    int lane = threadIdx.x & 31;
    int nwarps = (gridDim.x * blockDim.x) >> 5;
    for (int e = wg; e < n1; e += nwarps) {
        int row = g_f1row[e], ca = g_f1a[e], cb = g_f1b[e];
        float4 zv = ((const float4*)(Z + (size_t)row * D))[lane];
        float4 av = ((const float4*)(W + (size_t)ca * D))[lane];
        float4 bv = ((const float4*)(W + (size_t)cb * D))[lane];
        float z2 = 0.f, da = 0.f, db = 0.f;
        z2 = fmaf(zv.x, zv.x, z2); z2 = fmaf(zv.y, zv.y, z2);
        z2 = fmaf(zv.z, zv.z, z2); z2 = fmaf(zv.w, zv.w, z2);
        da = fmaf(zv.x, av.x, da); da = fmaf(zv.y, av.y, da);
        da = fmaf(zv.z, av.z, da); da = fmaf(zv.w, av.w, da);
        db = fmaf(zv.x, bv.x, db); db = fmaf(zv.y, bv.y, db);
        db = fmaf(zv.z, bv.z, db); db = fmaf(zv.w, bv.w, db);
        #pragma unroll
        for (int off = 16; off; off >>= 1) {
            z2 += __shfl_xor_sync(0xffffffffu, z2, off);
            da += __shfl_xor_sync(0xffffffffu, da, off);
            db += __shfl_xor_sync(0xffffffffu, db, off);
        }
        if (lane == 0) {
            float dista = __fadd_rn(__fsub_rn(z2, __fmul_rn(2.f, da)), g_w2[ca]);
            float distb = __fadd_rn(__fsub_rn(z2, __fmul_rn(2.f, db)), g_w2[cb]);
            g_idx[row] = (distb < dista || (distb == dista && cb < ca)) ? cb : ca;
        }
    }
}

// ---- tier 2: one block per flagged row; warps split codes, lanes split D ---
__global__ __launch_bounds__(256)
void tier2_kernel(const float* __restrict__ Z, const float* __restrict__ W) {
    __shared__ float zrow[D];
    __shared__ float wbv[8];
    __shared__ int   wbi[8];
    const int tid  = threadIdx.x;
    const int lane = tid & 31;
    const int w    = tid >> 5;          // warp id: owns codes [w*256, w*256+256)
    int n2 = g_n2;

    for (int f = blockIdx.x; f < n2; f += gridDim.x) {
        int row = g_f2row[f];
        __syncthreads();                 // protect zrow reuse across rows
        if (tid < 32) {
            float4 v = ((const float4*)(Z + (size_t)row * D))[tid];
            *(float4*)&zrow[tid * 4] = v;
        }
        __syncthreads();

        float4 zv = *(const float4*)&zrow[lane * 4];
        float z2 = 0.f;
        z2 = fmaf(zv.x, zv.x, z2); z2 = fmaf(zv.y, zv.y, z2);
        z2 = fmaf(zv.z, zv.z, z2); z2 = fmaf(zv.w, zv.w, z2);
        #pragma unroll
        for (int off = 16; off; off >>= 1)
            z2 += __shfl_xor_sync(0xffffffffu, z2, off);

        float bd = CUDART_INF_F;
        int   bi = 0x7fffffff;
        const int cbase = w * 256;
        // 2-way unroll: two independent shfl-reduce chains in flight
        for (int i = 0; i < 256; i += 2) {
            int c0 = cbase + i, c1 = cbase + i + 1;
            float4 w0 = ((const float4*)(W + (size_t)c0 * D))[lane];
            float4 w1 = ((const float4*)(W + (size_t)c1 * D))[lane];
            float p0 = 0.f, p1 = 0.f;
            p0 = fmaf(zv.x, w0.x, p0); p0 = fmaf(zv.y, w0.y, p0);
            p0 = fmaf(zv.z, w0.z, p0); p0 = fmaf(zv.w, w0.w, p0);
            p1 = fmaf(zv.x, w1.x, p1); p1 = fmaf(zv.y, w1.y, p1);
            p1 = fmaf(zv.z, w1.z, p1); p1 = fmaf(zv.w, w1.w, p1);
            #pragma unroll
            for (int off = 16; off; off >>= 1) {
                p0 += __shfl_xor_sync(0xffffffffu, p0, off);
                p1 += __shfl_xor_sync(0xffffffffu, p1, off);
            }
            float d0 = __fadd_rn(__fsub_rn(z2, __fmul_rn(2.f, p0)), g_w2[c0]);
            float d1 = __fadd_rn(__fsub_rn(z2, __fmul_rn(2.f, p1)), g_w2[c1]);
            if (d0 < bd || (d0 == bd && c0 < bi)) { bd = d0; bi = c0; }
            if (d1 < bd || (d1 == bd && c1 < bi)) { bd = d1; bi = c1; }
        }
        if (lane == 0) { wbv[w] = bd; wbi[w] = bi; }
        __syncthreads();
        if (tid == 0) {
            float v = wbv[0]; int j = wbi[0];
            #pragma unroll
            for (int q = 1; q < 8; q++) {
                float v2 = wbv[q]; int j2 = wbi[q];
                if (v2 < v || (v2 == v && j2 < j)) { v = v2; j = j2; }
            }
            g_idx[row] = j;
        }
    }
}

// ---- CSR bucket build: count -> prefix -> place ----------------------------
__global__ void count_kernel(int N) {
    int i = blockIdx.x * blockDim.x + threadIdx.x;
    if (i < N) atomicAdd(&g_counts[g_idx[i]], 1);
}

__global__ void prefix_kernel() {
    __shared__ int part[256];
    int t = threadIdx.x;
    int base = t * 8;
    int loc[8];
    int s = 0;
    #pragma unroll
    for (int i = 0; i < 8; i++) { loc[i] = s; s += g_counts[base + i]; }
    part[t] = s;
    __syncthreads();
    for (int off = 1; off < 256; off <<= 1) {
        int x = (t >= off) ? part[t - off] : 0;
        __syncthreads();
        part[t] += x;
        __syncthreads();
    }
    int excl = part[t] - s;
    #pragma unroll
    for (int i = 0; i < 8; i++) g_off[base + i] = excl + loc[i];
}

__global__ void place_kernel(int N) {
    int i = blockIdx.x * blockDim.x + threadIdx.x;
    if (i < N) {
        int j = g_idx[i];
        int slot = atomicAdd(&g_cursor[j], 1);
        g_bucket[g_off[j] + slot] = i;
    }
}

// ---- per-code int64 fixed-point gather-sum + EMA finalize ------------------
__global__ void codesum_kernel(const float* __restrict__ Z,
                               const float* __restrict__ Wold,
                               const float* __restrict__ Cold,
                               float* __restrict__ out_w,
                               float* __restrict__ out_c) {
    int k = blockIdx.x;
    int d = threadIdx.x;
    int cnt = g_counts[k];
    int off = g_off[k];
    float c_old = Cold[k];
    float c_new = (cnt > 0)
        ? __fadd_rn(__fmul_rn(VQ_ALPHA, c_old), __fmul_rn(VQ_OMA, (float)cnt))
        : c_old;
    if (d == 0) out_c[k] = c_new;

    float w = Wold[(size_t)k * D + d];
    float wn = w;
    if (cnt > 0) {
        long long afx = 0;
        int i = 0;
        for (; i + 1 < cnt; i += 2) {
            int r0 = g_bucket[off + i];
            int r1 = g_bucket[off + i + 1];
            afx += (long long)llrintf(Z[(size_t)r0 * D + d] * 1048576.0f)
                 + (long long)llrintf(Z[(size_t)r1 * D + d] * 1048576.0f);
        }
        if (i < cnt) {
            int r0 = g_bucket[off + i];
            afx += (long long)llrintf(Z[(size_t)r0 * D + d] * 1048576.0f);
        }
        float s  = (float)((double)afx * (1.0 / 1048576.0));
        float cm = fmaxf(c_new, 1e-12f);
        wn = __fadd_rn(__fmul_rn(VQ_ALPHA, w),
                       __fdiv_rn(__fmul_rn(VQ_OMA, s), cm));
    }
    out_w[(size_t)k * D + d] = wn;
}

// st_out = z + (w_new[i]-z); commit loss partials -> one double atomic/block.
__global__ void gather_loss_kernel(const float* __restrict__ Z,
                                   const float* __restrict__ Wn,
                                   float* __restrict__ out_st, int N) {
    int d   = threadIdx.x & 127;
    int sub = threadIdx.x >> 7;
    float accl = 0.f;
    for (int n = blockIdx.x * 2 + sub; n < N; n += gridDim.x * 2) {
        int j = g_idx[n];
        float w = Wn[(size_t)j * D + d];
        float z = Z[(size_t)n * D + d];
        out_st[(size_t)n * D + d] = __fadd_rn(z, __fsub_rn(w, z));
        float df = __fsub_rn(z, w);
        accl = fmaf(df, df, accl);
    }
    __shared__ float red[8];
    float s = accl;
    #pragma unroll
    for (int off = 16; off; off >>= 1) s += __shfl_xor_sync(0xffffffffu, s, off);
    if ((threadIdx.x & 31) == 0) red[threadIdx.x >> 5] = s;
    __syncthreads();
    if (threadIdx.x == 0) {
        float tot = ((red[0] + red[1]) + (red[2] + red[3]))
                  + ((red[4] + red[5]) + (red[6] + red[7]));
        atomicAdd(&g_loss, (double)tot);
    }
}

__global__ void loss_write_kernel(float* out_loss, int N) {
    *out_loss = (float)(g_loss / (double)N);
}

// ---------------------------------------------------------------------------

extern "C" void kernel_launch(void* const* d_in, const int* in_sizes, int n_in,
                              void* d_out, int out_size) {
    const float* Z = (const float*)d_in[0];
    const float* W = (const float*)d_in[1];
    const float* C = (const float*)d_in[2];
    const int N = in_sizes[0] / D;       // 65536
    const int K = in_sizes[2];           // 2048

    float* out      = (float*)d_out;
    float* out_st   = out;                           // [N*D]
    float* out_loss = out + (size_t)N * D;           // [1]
    float* out_w    = out_loss + 1;                  // [K*D]
    float* out_c    = out_w + (size_t)K * D;         // [K]

    static bool attr_done = false;
    if (!attr_done) {
        cudaFuncSetAttribute(argmin_hmma_kernel,
                             cudaFuncAttributeMaxDynamicSharedMemorySize, SMEM_ARG);
        attr_done = true;
    }

    prep_kernel<<<(K * 32 + 255) / 256, 256>>>(W, K);
    argmin_hmma_kernel<<<N / 128, 256, SMEM_ARG>>>(Z);
    tier1_kernel<<<256, 256>>>(Z, W);
    tier2_kernel<<<256, 256>>>(Z, W);
    count_kernel<<<N / 256, 256>>>(N);
    prefix_kernel<<<1, 256>>>();
    place_kernel<<<N / 256, 256>>>(N);
    codesum_kernel<<<K, D>>>(Z, W, C, out_w, out_c);
    gather_loss_kernel<<<4096, 256>>>(Z, out_w, out_st, N);
    loss_write_kernel<<<1, 1>>>(out_loss, N);
}

// round 16
// speedup vs baseline: 1.3129x; 1.0181x over previous
#include <cuda_runtime.h>
#include <cuda_fp16.h>
#include <cstdint>
#include <math_constants.h>

// ===========================================================================
// spk_vq_vae_resnet — R15 base + tier2 parallelism fix (grid 2048, 4-way ILP).
//   * argmin: fp16 HMMA (m16n8k16, f32 accum), 128-row CTAs, 16 code-tiles
//     of 128, cp.async double-buffered B, Z converted fp32->fp16 in-kernel,
//     2 CTAs/SM. Top-3 band 1e-3 + two-tier exact fp32 rescue.
//   * tier2: one block per flagged row (grid 2048 -> all rows concurrent);
//     8 warps x 256 codes, 4-way unroll (4 shfl chains in flight).
//   * EMA sums: CSR bucket build + per-code int64 fixed-point gather.
// Outputs (concat f32): st_out [N*D] | commit_loss [1] | w_new [K*D] | c_new [K]
// ===========================================================================

#define VQ_ALPHA 0.99f
#define VQ_OMA   0.01f

constexpr int D    = 128;
constexpr int NMAX = 65536;
constexpr int KMAX = 2048;
constexpr int NTILE = 16;          // code tiles of 128
constexpr float BAND = 1e-3f;

// ---- device scratch --------------------------------------------------------
__device__ __align__(16) __half g_Wh[KMAX * D];
__device__ float  g_w2[KMAX];
__device__ int    g_idx[NMAX];
__device__ int    g_f1row[NMAX], g_f1a[NMAX], g_f1b[NMAX];
__device__ int    g_f2row[NMAX];
__device__ int    g_n1, g_n2;
__device__ int    g_counts[KMAX];
__device__ int    g_off[KMAX];
__device__ int    g_cursor[KMAX];
__device__ int    g_bucket[NMAX];
__device__ double g_loss;

// ---- helpers ---------------------------------------------------------------
__device__ __forceinline__ uint32_t smem_u32(const void* p) {
    uint32_t a;
    asm("{ .reg .u64 t; cvta.to.shared.u64 t, %1; cvt.u32.u64 %0, t; }"
        : "=r"(a) : "l"(p));
    return a;
}
__device__ __forceinline__ void cp_async16(uint32_t smem_dst, const void* gsrc) {
    asm volatile("cp.async.cg.shared.global [%0], [%1], 16;" :: "r"(smem_dst), "l"(gsrc));
}
__device__ __forceinline__ void cp_commit() { asm volatile("cp.async.commit_group;"); }
template <int NN>
__device__ __forceinline__ void cp_wait() { asm volatile("cp.async.wait_group %0;" :: "n"(NN)); }

__device__ __forceinline__ void ldsm4(uint32_t& r0, uint32_t& r1, uint32_t& r2,
                                      uint32_t& r3, uint32_t addr) {
    asm volatile("ldmatrix.sync.aligned.m8n8.x4.shared.b16 {%0,%1,%2,%3}, [%4];"
                 : "=r"(r0), "=r"(r1), "=r"(r2), "=r"(r3) : "r"(addr));
}
__device__ __forceinline__ void mma16816(float* c, uint32_t a0, uint32_t a1,
                                         uint32_t a2, uint32_t a3,
                                         uint32_t b0, uint32_t b1) {
    asm volatile(
        "mma.sync.aligned.m16n8k16.row.col.f32.f16.f16.f32 "
        "{%0,%1,%2,%3}, {%4,%5,%6,%7}, {%8,%9}, {%0,%1,%2,%3};"
        : "+f"(c[0]), "+f"(c[1]), "+f"(c[2]), "+f"(c[3])
        : "r"(a0), "r"(a1), "r"(a2), "r"(a3), "r"(b0), "r"(b1));
}

// top-3 insert, lowest-index preference on exact ties
__device__ __forceinline__ void ins3(float s, int c,
                                     float& b1, int& i1, float& b2, int& i2,
                                     float& b3, int& i3) {
    if (s < b1 || (s == b1 && c < i1)) {
        b3 = b2; i3 = i2; b2 = b1; i2 = i1; b1 = s; i1 = c;
    } else if (s < b2 || (s == b2 && c < i2)) {
        b3 = b2; i3 = i2; b2 = s; i2 = c;
    } else if (s < b3 || (s == b3 && c < i3)) {
        b3 = s; i3 = c;
    }
}

// ---------------------------------------------------------------------------

// W fp32->fp16 + w2; block 0 also zeroes the small counters (fused zero).
__global__ void prep_kernel(const float* __restrict__ W, int K) {
    if (blockIdx.x == 0) {
        for (int j = threadIdx.x; j < K; j += blockDim.x) {
            g_counts[j] = 0; g_cursor[j] = 0;
        }
        if (threadIdx.x == 0) { g_loss = 0.0; g_n1 = 0; g_n2 = 0; }
    }
    int g    = (blockIdx.x * blockDim.x + threadIdx.x) >> 5;
    int lane = threadIdx.x & 31;
    if (g >= K) return;
    const float* src = W + (size_t)g * D;
    float4 v = ((const float4*)src)[lane];
    __half2 h01 = __floats2half2_rn(v.x, v.y);
    __half2 h23 = __floats2half2_rn(v.z, v.w);
    uint2 u = { *(uint32_t*)&h01, *(uint32_t*)&h23 };
    *(uint2*)(g_Wh + (size_t)g * D + lane * 4) = u;
    float s = 0.f;
    s = fmaf(v.x, v.x, s); s = fmaf(v.y, v.y, s);
    s = fmaf(v.z, v.z, s); s = fmaf(v.w, v.w, s);
    #pragma unroll
    for (int off = 16; off; off >>= 1) s += __shfl_xor_sync(0xffffffffu, s, off);
    if (lane == 0) g_w2[g] = s;
}

// ---- fp16 HMMA argmin, f32 accum, 128-code tiles, 2 CTAs/SM ----------------
// smem layout: Zs 32KB | Bs 2x32KB | w2s 8KB = 106496 B total
constexpr int SM_Z  = 0;
constexpr int SM_B0 = 32768;
constexpr int SM_W2 = 98304;
constexpr int SMEM_ARG = SM_W2 + KMAX * 4;   // 106496 bytes

// XOR-swizzled address (rows of 16 x 16B chunks, conflict-free ldsm)
__device__ __forceinline__ uint32_t sw_addr(uint32_t base, int r, int c) {
    return base + r * 256 + ((c ^ (r & 7)) << 4);
}

__global__ __launch_bounds__(256, 2)
void argmin_hmma_kernel(const float* __restrict__ Z) {
    extern __shared__ char sm[];
    const uint32_t sb = smem_u32(sm);
    float* w2s = (float*)(sm + SM_W2);
    const int tid  = threadIdx.x;
    const int lane = tid & 31;
    const int wid  = tid >> 5;
    const int warpRow = wid * 16;
    const int row0 = blockIdx.x * 128;

    // async: B tile 0 (group 0), B tile 1 (group 1)
    for (int i = tid; i < 2048; i += 256) {
        int r = i >> 4, c = i & 15;
        cp_async16(sw_addr(sb + SM_B0, r, c), g_Wh + (size_t)r * D + c * 8);
    }
    cp_commit();
    for (int i = tid; i < 2048; i += 256) {
        int r = i >> 4, c = i & 15;
        cp_async16(sw_addr(sb + SM_B0 + 32768, r, c),
                   g_Wh + (size_t)(128 + r) * D + c * 8);
    }
    cp_commit();

    // while B copies fly: stage w2 and convert this CTA's Z rows fp32->fp16
    for (int i = tid; i < KMAX; i += 256) w2s[i] = g_w2[i];
    {
        const float* Zb = Z + (size_t)row0 * D;
        #pragma unroll 4
        for (int i = tid; i < 4096; i += 256) {      // 128 rows x 32 float4
            int r = i >> 5, j = i & 31;
            float4 v = *(const float4*)(Zb + (size_t)r * D + j * 4);
            __half2 h01 = __floats2half2_rn(v.x, v.y);
            __half2 h23 = __floats2half2_rn(v.z, v.w);
            uint32_t addr = sw_addr(sb + SM_Z, r, j >> 1) + (j & 1) * 8;
            asm volatile("st.shared.v2.b32 [%0], {%1,%2};"
                         :: "r"(addr), "r"(*(uint32_t*)&h01), "r"(*(uint32_t*)&h23));
        }
    }

    float B1[2] = {CUDART_INF_F, CUDART_INF_F};
    float B2[2] = {CUDART_INF_F, CUDART_INF_F};
    float B3[2] = {CUDART_INF_F, CUDART_INF_F};
    int   I1[2] = {0x7fffffff, 0x7fffffff};
    int   I2[2] = {0x7fffffff, 0x7fffffff};
    int   I3[2] = {0x7fffffff, 0x7fffffff};

    const int m  = lane >> 3;
    const int r8 = lane & 7;

    for (int t = 0; t < NTILE; t++) {
        if (t < NTILE - 1) cp_wait<1>(); else cp_wait<0>();
        __syncthreads();                       // B[t] + Z(t==0) visible
        const uint32_t bbase = sb + SM_B0 + (t & 1) * 32768;

        float acc[16][4];
        #pragma unroll
        for (int f = 0; f < 16; f++)
            #pragma unroll
            for (int q = 0; q < 4; q++) acc[f][q] = 0.f;

        #pragma unroll
        for (int ks = 0; ks < 8; ks++) {
            uint32_t a0, a1, a2, a3;
            {
                int row = warpRow + ((m & 1) << 3) + r8;
                int ch  = 2 * ks + (m >> 1);
                ldsm4(a0, a1, a2, a3, sw_addr(sb + SM_Z, row, ch));
            }
            #pragma unroll
            for (int nf = 0; nf < 16; nf += 2) {
                uint32_t c0, c1, c2, c3;
                {
                    int code = nf * 8 + ((m >> 1) << 3) + r8;
                    int ch   = 2 * ks + (m & 1);
                    ldsm4(c0, c1, c2, c3, sw_addr(bbase, code, ch));
                }
                mma16816(acc[nf],     a0, a1, a2, a3, c0, c1);
                mma16816(acc[nf + 1], a0, a1, a2, a3, c2, c3);
            }
        }

        __syncthreads();                       // all warps done reading B[t]

        if (t < NTILE - 2) {
            const __half* src = g_Wh + (size_t)(t + 2) * 128 * D;
            uint32_t dstb = sb + SM_B0 + (t & 1) * 32768;
            for (int i = tid; i < 2048; i += 256) {
                int r = i >> 4, c = i & 15;
                cp_async16(sw_addr(dstb, r, c), src + (size_t)r * D + c * 8);
            }
            cp_commit();
        }

        // epilogue: s = w2 - 2*zw; rows r0 = warpRow+(lane>>2), r1 = r0+8
        #pragma unroll
        for (int f = 0; f < 16; f++) {
            int cb0 = t * 128 + f * 8 + 2 * (lane & 3);
            float w2a = w2s[cb0], w2b = w2s[cb0 + 1];
            float s;
            s = fmaf(-2.f, acc[f][0], w2a);
            ins3(s, cb0,     B1[0], I1[0], B2[0], I2[0], B3[0], I3[0]);
            s = fmaf(-2.f, acc[f][1], w2b);
            ins3(s, cb0 + 1, B1[0], I1[0], B2[0], I2[0], B3[0], I3[0]);
            s = fmaf(-2.f, acc[f][2], w2a);
            ins3(s, cb0,     B1[1], I1[1], B2[1], I2[1], B3[1], I3[1]);
            s = fmaf(-2.f, acc[f][3], w2b);
            ins3(s, cb0 + 1, B1[1], I1[1], B2[1], I2[1], B3[1], I3[1]);
        }
    }

    // merge top-3 across the 4 lanes of each quad (same rows)
    #pragma unroll
    for (int off = 1; off <= 2; off <<= 1) {
        #pragma unroll
        for (int r = 0; r < 2; r++) {
            float v1 = __shfl_xor_sync(0xffffffffu, B1[r], off);
            int   j1 = __shfl_xor_sync(0xffffffffu, I1[r], off);
            float v2 = __shfl_xor_sync(0xffffffffu, B2[r], off);
            int   j2 = __shfl_xor_sync(0xffffffffu, I2[r], off);
            float v3 = __shfl_xor_sync(0xffffffffu, B3[r], off);
            int   j3 = __shfl_xor_sync(0xffffffffu, I3[r], off);
            ins3(v1, j1, B1[r], I1[r], B2[r], I2[r], B3[r], I3[r]);
            ins3(v2, j2, B1[r], I1[r], B2[r], I2[r], B3[r], I3[r]);
            ins3(v3, j3, B1[r], I1[r], B2[r], I2[r], B3[r], I3[r]);
        }
    }

    if ((lane & 3) == 0) {
        #pragma unroll
        for (int r = 0; r < 2; r++) {
            int row = row0 + warpRow + (lane >> 2) + r * 8;
            g_idx[row] = I1[r];
            if (__fsub_rn(B3[r], B1[r]) < BAND) {
                int p = atomicAdd(&g_n2, 1);
                g_f2row[p] = row;
            } else if (__fsub_rn(B2[r], B1[r]) < BAND) {
                int p = atomicAdd(&g_n1, 1);
                g_f1row[p] = row; g_f1a[p] = I1[r]; g_f1b[p] = I2[r];
            }
        }
    }
}

// ---- tier 1: exact fp32 compare of the two in-band candidates --------------
__global__ void tier1_kernel(const float* __restrict__ Z,
                             const float* __restrict__ W) {
    int n1 = g_n1;
    int wg = (blockIdx.x * blockDim.x + threadIdx.x) >> 5;
    int lane = threadIdx.x & 31;
    int nwarps = (gridDim.x * blockDim.x) >> 5;
    for (int e = wg; e < n1; e += nwarps) {
        int row = g_f1row[e], ca = g_f1a[e], cb = g_f1b[e];
        float4 zv = ((const float4*)(Z + (size_t)row * D))[lane];
        float4 av = ((const float4*)(W + (size_t)ca * D))[lane];
        float4 bv = ((const float4*)(W + (size_t)cb * D))[lane];
        float z2 = 0.f, da = 0.f, db = 0.f;
        z2 = fmaf(zv.x, zv.x, z2); z2 = fmaf(zv.y, zv.y, z2);
        z2 = fmaf(zv.z, zv.z, z2); z2 = fmaf(zv.w, zv.w, z2);
        da = fmaf(zv.x, av.x, da); da = fmaf(zv.y, av.y, da);
        da = fmaf(zv.z, av.z, da); da = fmaf(zv.w, av.w, da);
        db = fmaf(zv.x, bv.x, db); db = fmaf(zv.y, bv.y, db);
        db = fmaf(zv.z, bv.z, db); db = fmaf(zv.w, bv.w, db);
        #pragma unroll
        for (int off = 16; off; off >>= 1) {
            z2 += __shfl_xor_sync(0xffffffffu, z2, off);
            da += __shfl_xor_sync(0xffffffffu, da, off);
            db += __shfl_xor_sync(0xffffffffu, db, off);
        }
        if (lane == 0) {
            float dista = __fadd_rn(__fsub_rn(z2, __fmul_rn(2.f, da)), g_w2[ca]);
            float distb = __fadd_rn(__fsub_rn(z2, __fmul_rn(2.f, db)), g_w2[cb]);
            g_idx[row] = (distb < dista || (distb == dista && cb < ca)) ? cb : ca;
        }
    }
}

// ---- tier 2: one block per flagged row; warps split codes, 4-way ILP -------
__global__ __launch_bounds__(256)
void tier2_kernel(const float* __restrict__ Z, const float* __restrict__ W) {
    __shared__ float zrow[D];
    __shared__ float wbv[8];
    __shared__ int   wbi[8];
    const int tid  = threadIdx.x;
    const int lane = tid & 31;
    const int w    = tid >> 5;          // warp id: owns codes [w*256, w*256+256)
    int n2 = g_n2;

    for (int f = blockIdx.x; f < n2; f += gridDim.x) {
        int row = g_f2row[f];
        __syncthreads();                 // protect zrow reuse across rows
        if (tid < 32) {
            float4 v = ((const float4*)(Z + (size_t)row * D))[tid];
            *(float4*)&zrow[tid * 4] = v;
        }
        __syncthreads();

        float4 zv = *(const float4*)&zrow[lane * 4];
        float z2 = 0.f;
        z2 = fmaf(zv.x, zv.x, z2); z2 = fmaf(zv.y, zv.y, z2);
        z2 = fmaf(zv.z, zv.z, z2); z2 = fmaf(zv.w, zv.w, z2);
        #pragma unroll
        for (int off = 16; off; off >>= 1)
            z2 += __shfl_xor_sync(0xffffffffu, z2, off);

        float bd = CUDART_INF_F;
        int   bi = 0x7fffffff;
        const int cbase = w * 256;
        // 4-way unroll: four independent shfl-reduce chains in flight
        for (int i = 0; i < 256; i += 4) {
            int c0 = cbase + i;
            float4 w0 = ((const float4*)(W + (size_t)(c0 + 0) * D))[lane];
            float4 w1 = ((const float4*)(W + (size_t)(c0 + 1) * D))[lane];
            float4 w2v = ((const float4*)(W + (size_t)(c0 + 2) * D))[lane];
            float4 w3 = ((const float4*)(W + (size_t)(c0 + 3) * D))[lane];
            float p0 = 0.f, p1 = 0.f, p2 = 0.f, p3 = 0.f;
            p0 = fmaf(zv.x, w0.x, p0); p0 = fmaf(zv.y, w0.y, p0);
            p0 = fmaf(zv.z, w0.z, p0); p0 = fmaf(zv.w, w0.w, p0);
            p1 = fmaf(zv.x, w1.x, p1); p1 = fmaf(zv.y, w1.y, p1);
            p1 = fmaf(zv.z, w1.z, p1); p1 = fmaf(zv.w, w1.w, p1);
            p2 = fmaf(zv.x, w2v.x, p2); p2 = fmaf(zv.y, w2v.y, p2);
            p2 = fmaf(zv.z, w2v.z, p2); p2 = fmaf(zv.w, w2v.w, p2);
            p3 = fmaf(zv.x, w3.x, p3); p3 = fmaf(zv.y, w3.y, p3);
            p3 = fmaf(zv.z, w3.z, p3); p3 = fmaf(zv.w, w3.w, p3);
            #pragma unroll
            for (int off = 16; off; off >>= 1) {
                p0 += __shfl_xor_sync(0xffffffffu, p0, off);
                p1 += __shfl_xor_sync(0xffffffffu, p1, off);
                p2 += __shfl_xor_sync(0xffffffffu, p2, off);
                p3 += __shfl_xor_sync(0xffffffffu, p3, off);
            }
            float d0 = __fadd_rn(__fsub_rn(z2, __fmul_rn(2.f, p0)), g_w2[c0 + 0]);
            float d1 = __fadd_rn(__fsub_rn(z2, __fmul_rn(2.f, p1)), g_w2[c0 + 1]);
            float d2 = __fadd_rn(__fsub_rn(z2, __fmul_rn(2.f, p2)), g_w2[c0 + 2]);
            float d3 = __fadd_rn(__fsub_rn(z2, __fmul_rn(2.f, p3)), g_w2[c0 + 3]);
            if (d0 < bd || (d0 == bd && (c0 + 0) < bi)) { bd = d0; bi = c0 + 0; }
            if (d1 < bd || (d1 == bd && (c0 + 1) < bi)) { bd = d1; bi = c0 + 1; }
            if (d2 < bd || (d2 == bd && (c0 + 2) < bi)) { bd = d2; bi = c0 + 2; }
            if (d3 < bd || (d3 == bd && (c0 + 3) < bi)) { bd = d3; bi = c0 + 3; }
        }
        if (lane == 0) { wbv[w] = bd; wbi[w] = bi; }
        __syncthreads();
        if (tid == 0) {
            float v = wbv[0]; int j = wbi[0];
            #pragma unroll
            for (int q = 1; q < 8; q++) {
                float v2 = wbv[q]; int j2 = wbi[q];
                if (v2 < v || (v2 == v && j2 < j)) { v = v2; j = j2; }
            }
            g_idx[row] = j;
        }
    }
}

// ---- CSR bucket build: count -> prefix -> place ----------------------------
__global__ void count_kernel(int N) {
    int i = blockIdx.x * blockDim.x + threadIdx.x;
    if (i < N) atomicAdd(&g_counts[g_idx[i]], 1);
}

__global__ void prefix_kernel() {
    __shared__ int part[256];
    int t = threadIdx.x;
    int base = t * 8;
    int loc[8];
    int s = 0;
    #pragma unroll
    for (int i = 0; i < 8; i++) { loc[i] = s; s += g_counts[base + i]; }
    part[t] = s;
    __syncthreads();
    for (int off = 1; off < 256; off <<= 1) {
        int x = (t >= off) ? part[t - off] : 0;
        __syncthreads();
        part[t] += x;
        __syncthreads();
    }
    int excl = part[t] - s;
    #pragma unroll
    for (int i = 0; i < 8; i++) g_off[base + i] = excl + loc[i];
}

__global__ void place_kernel(int N) {
    int i = blockIdx.x * blockDim.x + threadIdx.x;
    if (i < N) {
        int j = g_idx[i];
        int slot = atomicAdd(&g_cursor[j], 1);
        g_bucket[g_off[j] + slot] = i;
    }
}

// ---- per-code int64 fixed-point gather-sum + EMA finalize ------------------
__global__ void codesum_kernel(const float* __restrict__ Z,
                               const float* __restrict__ Wold,
                               const float* __restrict__ Cold,
                               float* __restrict__ out_w,
                               float* __restrict__ out_c) {
    int k = blockIdx.x;
    int d = threadIdx.x;
    int cnt = g_counts[k];
    int off = g_off[k];
    float c_old = Cold[k];
    float c_new = (cnt > 0)
        ? __fadd_rn(__fmul_rn(VQ_ALPHA, c_old), __fmul_rn(VQ_OMA, (float)cnt))
        : c_old;
    if (d == 0) out_c[k] = c_new;

    float w = Wold[(size_t)k * D + d];
    float wn = w;
    if (cnt > 0) {
        long long afx = 0;
        int i = 0;
        for (; i + 1 < cnt; i += 2) {
            int r0 = g_bucket[off + i];
            int r1 = g_bucket[off + i + 1];
            afx += (long long)llrintf(Z[(size_t)r0 * D + d] * 1048576.0f)
                 + (long long)llrintf(Z[(size_t)r1 * D + d] * 1048576.0f);
        }
        if (i < cnt) {
            int r0 = g_bucket[off + i];
            afx += (long long)llrintf(Z[(size_t)r0 * D + d] * 1048576.0f);
        }
        float s  = (float)((double)afx * (1.0 / 1048576.0));
        float cm = fmaxf(c_new, 1e-12f);
        wn = __fadd_rn(__fmul_rn(VQ_ALPHA, w),
                       __fdiv_rn(__fmul_rn(VQ_OMA, s), cm));
    }
    out_w[(size_t)k * D + d] = wn;
}

// st_out = z + (w_new[i]-z); commit loss partials -> one double atomic/block.
__global__ void gather_loss_kernel(const float* __restrict__ Z,
                                   const float* __restrict__ Wn,
                                   float* __restrict__ out_st, int N) {
    int d   = threadIdx.x & 127;
    int sub = threadIdx.x >> 7;
    float accl = 0.f;
    for (int n = blockIdx.x * 2 + sub; n < N; n += gridDim.x * 2) {
        int j = g_idx[n];
        float w = Wn[(size_t)j * D + d];
        float z = Z[(size_t)n * D + d];
        out_st[(size_t)n * D + d] = __fadd_rn(z, __fsub_rn(w, z));
        float df = __fsub_rn(z, w);
        accl = fmaf(df, df, accl);
    }
    __shared__ float red[8];
    float s = accl;
    #pragma unroll
    for (int off = 16; off; off >>= 1) s += __shfl_xor_sync(0xffffffffu, s, off);
    if ((threadIdx.x & 31) == 0) red[threadIdx.x >> 5] = s;
    __syncthreads();
    if (threadIdx.x == 0) {
        float tot = ((red[0] + red[1]) + (red[2] + red[3]))
                  + ((red[4] + red[5]) + (red[6] + red[7]));
        atomicAdd(&g_loss, (double)tot);
    }
}

__global__ void loss_write_kernel(float* out_loss, int N) {
    *out_loss = (float)(g_loss / (double)N);
}

// ---------------------------------------------------------------------------

extern "C" void kernel_launch(void* const* d_in, const int* in_sizes, int n_in,
                              void* d_out, int out_size) {
    const float* Z = (const float*)d_in[0];
    const float* W = (const float*)d_in[1];
    const float* C = (const float*)d_in[2];
    const int N = in_sizes[0] / D;       // 65536
    const int K = in_sizes[2];           // 2048

    float* out      = (float*)d_out;
    float* out_st   = out;                           // [N*D]
    float* out_loss = out + (size_t)N * D;           // [1]
    float* out_w    = out_loss + 1;                  // [K*D]
    float* out_c    = out_w + (size_t)K * D;         // [K]

    static bool attr_done = false;
    if (!attr_done) {
        cudaFuncSetAttribute(argmin_hmma_kernel,
                             cudaFuncAttributeMaxDynamicSharedMemorySize, SMEM_ARG);
        attr_done = true;
    }

    prep_kernel<<<(K * 32 + 255) / 256, 256>>>(W, K);
    argmin_hmma_kernel<<<N / 128, 256, SMEM_ARG>>>(Z);
    tier1_kernel<<<256, 256>>>(Z, W);
    tier2_kernel<<<2048, 256>>>(Z, W);
    count_kernel<<<N / 256, 256>>>(N);
    prefix_kernel<<<1, 256>>>();
    place_kernel<<<N / 256, 256>>>(N);
    codesum_kernel<<<K, D>>>(Z, W, C, out_w, out_c);
    gather_loss_kernel<<<4096, 256>>>(Z, out_w, out_st, N);
    loss_write_kernel<<<1, 1>>>(out_loss, N);
}